// round 11
// baseline (speedup 1.0000x reference)
#include <cuda_runtime.h>
#include <cuda_bf16.h>
#include <math.h>
#include <mma.h>

using namespace nvcuda;

// ---------------------------------------------------------------------------
// SchNet interaction block (sm_100 base target — no tcgen05).
//  - edge filter: prep kernel packs {row,col,ti,u}; edge kernel = pure
//    pipelined lerp-gather-reduce with a single barrier (new this round)
//  - node GEMMs: tf32 wmma (unroll-2, validated); last two fused
//  - fork stream s2: pos-copy + memset + build_table + edge_prep
// ---------------------------------------------------------------------------

#define HID   256
#define NG    50
#define TILE  32
#define SPAD  36
#define NTHREADS 256

#define CUTOFF_F 10.0f
#define LN2_F    0.69314718055994530942f
#define PI_F     3.14159265358979323846f

#define NT    2048
#define DMAX  17.3206f

#define MAXN 25000
#define MAXE 400000
#define EB   32
#define MAXE_PAD ((MAXE + EB - 1) / EB * EB)

__device__ float g_x[(size_t)MAXN * HID];
__device__ float g_agg[(size_t)MAXN * HID];
__device__ float g_table[(size_t)NT * HID];
__device__ float g_wtf[3][HID * HID];        // tf32-rounded weights, [k][n]
__device__ int4  g_eprep[MAXE_PAD];          // {row, col, ti, bitcast(u)}

__device__ __forceinline__ float ssp(float v) {
    return fmaxf(v, 0.0f) + log1pf(expf(-fabsf(v))) - LN2_F;
}

__device__ __forceinline__ float to_tf32(float x) {
    unsigned u;
    asm("cvt.rna.tf32.f32 %0, %1;" : "=r"(u) : "f"(x));
    return __uint_as_float(u);
}

// ---------------------------------------------------------------------------
__global__ void prep_weights(const float* __restrict__ w0,
                             const float* __restrict__ w1,
                             const float* __restrict__ w2)
{
    int which = blockIdx.y;
    const float* w = (which == 0) ? w0 : (which == 1) ? w1 : w2;
    int k = blockIdx.x;
    int n = threadIdx.x;
    g_wtf[which][k * HID + n] = to_tf32(w[k * HID + n]);
}

// ---------------------------------------------------------------------------
// Edge geometry prep: one thread per edge, coalesced int4 output.
// Padded entries (e >= nedges) are zeroed (safe dummy work, reduce-guarded).
// ---------------------------------------------------------------------------
__global__ __launch_bounds__(NTHREADS) void edge_prep(
    const float* __restrict__ pos, const int* __restrict__ edge_index,
    int4* __restrict__ eprep, int nedges, int ntotal)
{
    int e = blockIdx.x * NTHREADS + threadIdx.x;
    if (e >= ntotal) return;
    if (e >= nedges) { eprep[e] = make_int4(0, 0, 0, 0); return; }

    const float inv_dx = (float)(NT - 1) / DMAX;
    int r = edge_index[e];
    int c = edge_index[nedges + e];
    float dxp = pos[3*r+0] - pos[3*c+0];
    float dyp = pos[3*r+1] - pos[3*c+1];
    float dzp = pos[3*r+2] - pos[3*c+2];
    float d = sqrtf(dxp*dxp + dyp*dyp + dzp*dzp);
    float s = d * inv_dx;
    int ti = (int)s;
    if (ti > NT - 2) ti = NT - 2;
    float u = s - (float)ti;
    eprep[e] = make_int4(r, c, ti, __float_as_int(u));
}

// ---------------------------------------------------------------------------
// tf32 wmma node GEMM, optionally fused 2-stage (validated; unroll 2).
// ---------------------------------------------------------------------------
#define GLD 264
#define NODE_SMEM (64 * GLD * 4)

__global__ __launch_bounds__(NTHREADS) void node_wmma(
    const float* __restrict__ A,
    const float* __restrict__ W1, const float* __restrict__ b1, int act1,
    const float* __restrict__ W2, const float* __restrict__ b2,
    float* __restrict__ out, int nnodes)
{
    extern __shared__ float buf[];
    const int tid = threadIdx.x;
    const int wid = tid >> 5;
    const int warp_r = wid >> 2;
    const int warp_c = wid & 3;
    const int n0 = blockIdx.x * 64;

    for (int i = tid; i < 64 * 64; i += NTHREADS) {
        int row = i >> 6, c4 = (i & 63) << 2;
        float4 v = make_float4(0.f, 0.f, 0.f, 0.f);
        if (n0 + row < nnodes)
            v = *(const float4*)(A + (size_t)(n0 + row) * HID + c4);
        buf[row * GLD + c4 + 0] = to_tf32(v.x);
        buf[row * GLD + c4 + 1] = to_tf32(v.y);
        buf[row * GLD + c4 + 2] = to_tf32(v.z);
        buf[row * GLD + c4 + 3] = to_tf32(v.w);
    }
    __syncthreads();

    wmma::fragment<wmma::accumulator, 16, 16, 8, float> acc[2][4];

    #pragma unroll
    for (int m = 0; m < 2; m++)
        #pragma unroll
        for (int j = 0; j < 4; j++)
            wmma::fill_fragment(acc[m][j], 0.0f);

    #pragma unroll 2
    for (int kk = 0; kk < HID / 8; kk++) {
        wmma::fragment<wmma::matrix_a, 16, 16, 8, wmma::precision::tf32, wmma::row_major> af[2];
        #pragma unroll
        for (int m = 0; m < 2; m++)
            wmma::load_matrix_sync(af[m], buf + (warp_r * 32 + m * 16) * GLD + kk * 8, GLD);
        wmma::fragment<wmma::matrix_b, 16, 16, 8, wmma::precision::tf32, wmma::row_major> bf;
        #pragma unroll
        for (int j = 0; j < 4; j++) {
            wmma::load_matrix_sync(bf, W1 + (size_t)kk * 8 * HID + warp_c * 64 + j * 16, HID);
            #pragma unroll
            for (int m = 0; m < 2; m++)
                wmma::mma_sync(acc[m][j], af[m], bf, acc[m][j]);
        }
    }
    __syncthreads();
    #pragma unroll
    for (int m = 0; m < 2; m++)
        #pragma unroll
        for (int j = 0; j < 4; j++)
            wmma::store_matrix_sync(buf + (warp_r * 32 + m * 16) * GLD + warp_c * 64 + j * 16,
                                    acc[m][j], GLD, wmma::mem_row_major);
    __syncthreads();

    if (W2 == nullptr) {
        float bb = b1 ? b1[tid] : 0.0f;
        #pragma unroll 4
        for (int r = 0; r < 64; r++) {
            if (n0 + r < nnodes) {
                float v = buf[r * GLD + tid] + bb;
                if (act1) v = ssp(v);
                out[(size_t)(n0 + r) * HID + tid] = v;
            }
        }
        return;
    }

    {
        float bb = b1 ? b1[tid] : 0.0f;
        #pragma unroll 4
        for (int r = 0; r < 64; r++) {
            float v = buf[r * GLD + tid] + bb;
            if (act1) v = ssp(v);
            buf[r * GLD + tid] = to_tf32(v);
        }
    }
    __syncthreads();

    #pragma unroll
    for (int m = 0; m < 2; m++)
        #pragma unroll
        for (int j = 0; j < 4; j++)
            wmma::fill_fragment(acc[m][j], 0.0f);

    #pragma unroll 2
    for (int kk = 0; kk < HID / 8; kk++) {
        wmma::fragment<wmma::matrix_a, 16, 16, 8, wmma::precision::tf32, wmma::row_major> af[2];
        #pragma unroll
        for (int m = 0; m < 2; m++)
            wmma::load_matrix_sync(af[m], buf + (warp_r * 32 + m * 16) * GLD + kk * 8, GLD);
        wmma::fragment<wmma::matrix_b, 16, 16, 8, wmma::precision::tf32, wmma::row_major> bf;
        #pragma unroll
        for (int j = 0; j < 4; j++) {
            wmma::load_matrix_sync(bf, W2 + (size_t)kk * 8 * HID + warp_c * 64 + j * 16, HID);
            #pragma unroll
            for (int m = 0; m < 2; m++)
                wmma::mma_sync(acc[m][j], af[m], bf, acc[m][j]);
        }
    }
    __syncthreads();
    #pragma unroll
    for (int m = 0; m < 2; m++)
        #pragma unroll
        for (int j = 0; j < 4; j++)
            wmma::store_matrix_sync(buf + (warp_r * 32 + m * 16) * GLD + warp_c * 64 + j * 16,
                                    acc[m][j], GLD, wmma::mem_row_major);
    __syncthreads();

    {
        float bb = b2 ? b2[tid] : 0.0f;
        #pragma unroll 4
        for (int r = 0; r < 64; r++) {
            if (n0 + r < nnodes)
                out[(size_t)(n0 + r) * HID + tid] = buf[r * GLD + tid] + bb;
        }
    }
}

// ---------------------------------------------------------------------------
// Build LUT (fp32 SIMT, validated)
// ---------------------------------------------------------------------------
__global__ __launch_bounds__(NTHREADS) void build_table(
    const float* __restrict__ w1, const float* __restrict__ b1,
    const float* __restrict__ w2, const float* __restrict__ b2,
    float* __restrict__ table)
{
    __shared__ __align__(16) float eaT[NG * SPAD];
    __shared__ __align__(16) float t1T[HID * SPAD];
    __shared__ float C_s[TILE];

    const int tid = threadIdx.x;
    const int t0  = blockIdx.x * TILE;
    const float dx = DMAX / (float)(NT - 1);

    if (tid < TILE) {
        float d = (float)(t0 + tid) * dx;
        C_s[tid] = 0.5f * (cosf(d * (PI_F / CUTOFF_F)) + 1.0f);
    }

    const float step  = CUTOFF_F / (float)(NG - 1);
    const float coeff = -0.5f / (step * step);
    for (int idx = tid; idx < TILE * NG; idx += NTHREADS) {
        int e = idx / NG, g = idx % NG;
        float d = (float)(t0 + e) * dx;
        float diff = d - (float)g * step;
        eaT[g * SPAD + e] = expf(coeff * diff * diff);
    }
    __syncthreads();

    const int f = tid;
    float acc[TILE];
    {
        float bv = b1[f];
        #pragma unroll
        for (int e = 0; e < TILE; e++) acc[e] = bv;
        #pragma unroll 2
        for (int g = 0; g < NG; g++) {
            float wv = w1[g * HID + f];
            const float4* p = (const float4*)&eaT[g * SPAD];
            #pragma unroll
            for (int q = 0; q < TILE / 4; q++) {
                float4 v = p[q];
                acc[4*q+0] = fmaf(v.x, wv, acc[4*q+0]);
                acc[4*q+1] = fmaf(v.y, wv, acc[4*q+1]);
                acc[4*q+2] = fmaf(v.z, wv, acc[4*q+2]);
                acc[4*q+3] = fmaf(v.w, wv, acc[4*q+3]);
            }
        }
        #pragma unroll
        for (int e = 0; e < TILE; e++) t1T[f * SPAD + e] = ssp(acc[e]);
    }
    __syncthreads();
    {
        float bv = b2[f];
        #pragma unroll
        for (int e = 0; e < TILE; e++) acc[e] = bv;
        #pragma unroll 4
        for (int j = 0; j < HID; j++) {
            float wv = w2[j * HID + f];
            const float4* p = (const float4*)&t1T[j * SPAD];
            #pragma unroll
            for (int q = 0; q < TILE / 4; q++) {
                float4 v = p[q];
                acc[4*q+0] = fmaf(v.x, wv, acc[4*q+0]);
                acc[4*q+1] = fmaf(v.y, wv, acc[4*q+1]);
                acc[4*q+2] = fmaf(v.z, wv, acc[4*q+2]);
                acc[4*q+3] = fmaf(v.w, wv, acc[4*q+3]);
            }
        }
        #pragma unroll
        for (int e = 0; e < TILE; e++)
            table[(size_t)(t0 + e) * HID + f] = acc[e] * C_s[e];
    }
}

// ---------------------------------------------------------------------------
// Edge kernel v4: no prologue, no first barrier. Per-edge int4 broadcast
// loads + 2-deep pipeline. One sync, then TMA bulk-reduce per edge.
// ---------------------------------------------------------------------------
#define EDGE_SMEM_BYTES (EB * HID * 4)   // 32 KB

__global__ __launch_bounds__(NTHREADS, 6) void edge_lut_kernel(
    const float* __restrict__ x,
    const int4* __restrict__ eprep,
    const float* __restrict__ table,
    float* __restrict__ agg, int nedges)
{
    extern __shared__ float msg[];       // [EB][HID]

    const int tid   = threadIdx.x;
    const int grp   = tid >> 6;          // 0..3
    const int lane4 = tid & 63;          // float4 column
    const int e0    = blockIdx.x * EB;

    const float4* tab4 = (const float4*)table;   // [NT][64]
    const float4* x4   = (const float4*)x;       // [N][64]
    const int4*   ep   = eprep + e0;

    // 2-deep pipeline over 8 iterations (edges grp, grp+4, ...)
    int4 p0 = __ldg(&ep[grp]);           // broadcast within 64-thread group
    float4 a0, b0, v0;
    {
        size_t tbase = (size_t)p0.z * (HID / 4) + lane4;
        a0 = tab4[tbase];
        b0 = tab4[tbase + HID / 4];
        v0 = x4[(size_t)p0.x * (HID / 4) + lane4];
    }
    #pragma unroll
    for (int it = 0; it < EB / 4; it++) {
        int4 p1;
        float4 a1, b1, v1;
        if (it < EB / 4 - 1) {
            p1 = __ldg(&ep[grp + (it + 1) * 4]);
            size_t tbase = (size_t)p1.z * (HID / 4) + lane4;
            a1 = tab4[tbase];
            b1 = tab4[tbase + HID / 4];
            v1 = x4[(size_t)p1.x * (HID / 4) + lane4];
        }
        int i = grp + it * 4;
        float u = __int_as_float(p0.w);
        float4 m;
        m.x = v0.x * fmaf(b0.x - a0.x, u, a0.x);
        m.y = v0.y * fmaf(b0.y - a0.y, u, a0.y);
        m.z = v0.z * fmaf(b0.z - a0.z, u, a0.z);
        m.w = v0.w * fmaf(b0.w - a0.w, u, a0.w);
        ((float4*)(msg + i * HID))[lane4] = m;
        p0 = p1; a0 = a1; b0 = b1; v0 = v1;
    }
    __syncthreads();
    asm volatile("fence.proxy.async.shared::cta;" ::: "memory");

    if (tid < EB && (e0 + tid) < nedges) {
        int col = ep[tid].y;
        unsigned saddr = (unsigned)__cvta_generic_to_shared(msg + tid * HID);
        float* gdst = agg + (size_t)col * HID;
        asm volatile(
            "cp.reduce.async.bulk.global.shared::cta.bulk_group.add.f32 [%0], [%1], %2;"
            :: "l"(gdst), "r"(saddr), "r"(HID * 4) : "memory");
        asm volatile("cp.async.bulk.commit_group;" ::: "memory");
        asm volatile("cp.async.bulk.wait_group 0;" ::: "memory");
    }
}

// ---------------------------------------------------------------------------
extern "C" void kernel_launch(void* const* d_in, const int* in_sizes, int n_in,
                              void* d_out, int out_size)
{
    const float* h      = (const float*)d_in[0];
    const float* pos    = (const float*)d_in[1];
    const float* lin1_w = (const float*)d_in[2];
    const float* lin2_w = (const float*)d_in[3];
    const float* lin2_b = (const float*)d_in[4];
    const float* mlp_w1 = (const float*)d_in[5];
    const float* mlp_b1 = (const float*)d_in[6];
    const float* mlp_w2 = (const float*)d_in[7];
    const float* mlp_b2 = (const float*)d_in[8];
    const float* lin_w  = (const float*)d_in[9];
    const float* lin_b  = (const float*)d_in[10];
    const int*   eidx   = (const int*)d_in[11];

    const int nnodes = in_sizes[0] / HID;
    const int nedges = in_sizes[11] / 2;

    float *xbuf = nullptr, *aggb = nullptr, *tabl = nullptr, *wtf = nullptr;
    int4  *eprep = nullptr;
    cudaGetSymbolAddress((void**)&xbuf, g_x);
    cudaGetSymbolAddress((void**)&aggb, g_agg);
    cudaGetSymbolAddress((void**)&tabl, g_table);
    cudaGetSymbolAddress((void**)&wtf, g_wtf);
    cudaGetSymbolAddress((void**)&eprep, g_eprep);

    float* out_f = (float*)d_out;

    static cudaStream_t s2 = nullptr;
    static cudaEvent_t evFork = nullptr, evJoin = nullptr;
    if (!s2) {
        cudaFuncSetAttribute(edge_lut_kernel,
                             cudaFuncAttributeMaxDynamicSharedMemorySize,
                             EDGE_SMEM_BYTES);
        cudaFuncSetAttribute(node_wmma,
                             cudaFuncAttributeMaxDynamicSharedMemorySize,
                             NODE_SMEM);
        cudaStreamCreateWithFlags(&s2, cudaStreamNonBlocking);
        cudaEventCreateWithFlags(&evFork, cudaEventDisableTiming);
        cudaEventCreateWithFlags(&evJoin, cudaEventDisableTiming);
    }

    const int nblk_wmma  = (nnodes + 63) / 64;
    const int nblk_edges = (nedges + EB - 1) / EB;
    const int ntotal     = nblk_edges * EB;

    // fork: pos copy + memset + build_table + edge_prep on s2
    cudaEventRecord(evFork, 0);
    cudaStreamWaitEvent(s2, evFork, 0);
    if (out_size >= nnodes * HID + nnodes * 3) {
        cudaMemcpyAsync(out_f + (size_t)nnodes * HID, pos,
                        (size_t)nnodes * 3 * sizeof(float),
                        cudaMemcpyDeviceToDevice, s2);
    }
    cudaMemsetAsync(aggb, 0, (size_t)nnodes * HID * sizeof(float), s2);
    build_table<<<NT / TILE, NTHREADS, 0, s2>>>(mlp_w1, mlp_b1, mlp_w2, mlp_b2, tabl);
    edge_prep<<<(ntotal + NTHREADS - 1) / NTHREADS, NTHREADS, 0, s2>>>(
        pos, eidx, eprep, nedges, ntotal);
    cudaEventRecord(evJoin, s2);

    prep_weights<<<dim3(HID, 3), HID>>>(lin1_w, lin2_w, lin_w);
    node_wmma<<<nblk_wmma, NTHREADS, NODE_SMEM>>>(
        h, wtf + 0 * HID * HID, nullptr, 0, nullptr, nullptr, xbuf, nnodes);

    cudaStreamWaitEvent(0, evJoin, 0);   // join before edge kernel

    edge_lut_kernel<<<nblk_edges, NTHREADS, EDGE_SMEM_BYTES>>>(
        xbuf, eprep, tabl, aggb, nedges);

    node_wmma<<<nblk_wmma, NTHREADS, NODE_SMEM>>>(
        aggb, wtf + 1 * HID * HID, lin2_b, 1,
        wtf + 2 * HID * HID, lin_b, out_f, nnodes);
}

// round 13
// speedup vs baseline: 1.0486x; 1.0486x over previous
#include <cuda_runtime.h>
#include <cuda_bf16.h>
#include <math.h>
#include <mma.h>

using namespace nvcuda;

// ---------------------------------------------------------------------------
// SchNet interaction block (sm_100 base target — no tcgen05).
//  - edge filter: distance LUT (2048 pts) + pipelined float4 lerp + TMA reduce
//    (round-9 validated, 129us — edge micro-tuning exhausted, do not touch)
//  - node GEMMs: tf32 wmma, 32-row CTA / 32x32 warp tile for occupancy
//  - build_table + memset forked onto 2nd stream
//  (Round-12 kernel resubmitted verbatim: container failed before running it.)
// ---------------------------------------------------------------------------

#define HID   256
#define NG    50
#define TILE  32
#define SPAD  36
#define NTHREADS 256

#define CUTOFF_F 10.0f
#define LN2_F    0.69314718055994530942f
#define PI_F     3.14159265358979323846f

#define NT    2048
#define DMAX  17.3206f

#define MAXN 25000
__device__ float g_x[(size_t)MAXN * HID];
__device__ float g_agg[(size_t)MAXN * HID];
__device__ float g_table[(size_t)NT * HID];
__device__ float g_wtf[3][HID * HID];        // tf32-rounded weights, [k][n]

__device__ __forceinline__ float ssp(float v) {
    return fmaxf(v, 0.0f) + log1pf(expf(-fabsf(v))) - LN2_F;
}

__device__ __forceinline__ float to_tf32(float x) {
    unsigned u;
    asm("cvt.rna.tf32.f32 %0, %1;" : "=r"(u) : "f"(x));
    return __uint_as_float(u);
}

// ---------------------------------------------------------------------------
__global__ void prep_weights(const float* __restrict__ w0,
                             const float* __restrict__ w1,
                             const float* __restrict__ w2)
{
    int which = blockIdx.y;
    const float* w = (which == 0) ? w0 : (which == 1) ? w1 : w2;
    int k = blockIdx.x;
    int n = threadIdx.x;
    g_wtf[which][k * HID + n] = to_tf32(w[k * HID + n]);
}

// ---------------------------------------------------------------------------
// tf32 wmma node GEMM, optionally fused 2-stage.
// v2: 32 rows/CTA, 8 warps each owning a 32-col strip (warp tile 32x32,
// acc 2x2). Halves regs+smem vs the 64-row version -> 3-4 CTAs/SM (was 2).
// ---------------------------------------------------------------------------
#define NROWS 32
#define GLD 264
#define NODE_SMEM (NROWS * GLD * 4)      // 33792 B

__global__ __launch_bounds__(NTHREADS) void node_wmma(
    const float* __restrict__ A,
    const float* __restrict__ W1, const float* __restrict__ b1, int act1,
    const float* __restrict__ W2, const float* __restrict__ b2,
    float* __restrict__ out, int nnodes)
{
    extern __shared__ float buf[];       // [NROWS][GLD]
    const int tid = threadIdx.x;
    const int wid = tid >> 5;            // 0..7: column strip wid*32
    const int n0 = blockIdx.x * NROWS;
    const int c0 = wid * 32;

    // ---- stage A rows as tf32 ----
    for (int i = tid; i < NROWS * 64; i += NTHREADS) {   // 32 rows x 64 float4
        int row = i >> 6, c4 = (i & 63) << 2;
        float4 v = make_float4(0.f, 0.f, 0.f, 0.f);
        if (n0 + row < nnodes)
            v = *(const float4*)(A + (size_t)(n0 + row) * HID + c4);
        buf[row * GLD + c4 + 0] = to_tf32(v.x);
        buf[row * GLD + c4 + 1] = to_tf32(v.y);
        buf[row * GLD + c4 + 2] = to_tf32(v.z);
        buf[row * GLD + c4 + 3] = to_tf32(v.w);
    }
    __syncthreads();

    wmma::fragment<wmma::accumulator, 16, 16, 8, float> acc[2][2];

    // ---- stage 1: A @ W1 ----
    #pragma unroll
    for (int m = 0; m < 2; m++)
        #pragma unroll
        for (int j = 0; j < 2; j++)
            wmma::fill_fragment(acc[m][j], 0.0f);

    #pragma unroll 2
    for (int kk = 0; kk < HID / 8; kk++) {
        wmma::fragment<wmma::matrix_a, 16, 16, 8, wmma::precision::tf32, wmma::row_major> af[2];
        #pragma unroll
        for (int m = 0; m < 2; m++)
            wmma::load_matrix_sync(af[m], buf + (m * 16) * GLD + kk * 8, GLD);
        wmma::fragment<wmma::matrix_b, 16, 16, 8, wmma::precision::tf32, wmma::row_major> bf;
        #pragma unroll
        for (int j = 0; j < 2; j++) {
            wmma::load_matrix_sync(bf, W1 + (size_t)kk * 8 * HID + c0 + j * 16, HID);
            #pragma unroll
            for (int m = 0; m < 2; m++)
                wmma::mma_sync(acc[m][j], af[m], bf, acc[m][j]);
        }
    }
    __syncthreads();
    #pragma unroll
    for (int m = 0; m < 2; m++)
        #pragma unroll
        for (int j = 0; j < 2; j++)
            wmma::store_matrix_sync(buf + (m * 16) * GLD + c0 + j * 16,
                                    acc[m][j], GLD, wmma::mem_row_major);
    __syncthreads();

    if (W2 == nullptr) {
        float bb = b1 ? b1[tid] : 0.0f;
        #pragma unroll 4
        for (int r = 0; r < NROWS; r++) {
            if (n0 + r < nnodes) {
                float v = buf[r * GLD + tid] + bb;
                if (act1) v = ssp(v);
                out[(size_t)(n0 + r) * HID + tid] = v;
            }
        }
        return;
    }

    // ---- elementwise between stages ----
    {
        float bb = b1 ? b1[tid] : 0.0f;
        #pragma unroll 4
        for (int r = 0; r < NROWS; r++) {
            float v = buf[r * GLD + tid] + bb;
            if (act1) v = ssp(v);
            buf[r * GLD + tid] = to_tf32(v);
        }
    }
    __syncthreads();

    // ---- stage 2: Y @ W2 ----
    #pragma unroll
    for (int m = 0; m < 2; m++)
        #pragma unroll
        for (int j = 0; j < 2; j++)
            wmma::fill_fragment(acc[m][j], 0.0f);

    #pragma unroll 2
    for (int kk = 0; kk < HID / 8; kk++) {
        wmma::fragment<wmma::matrix_a, 16, 16, 8, wmma::precision::tf32, wmma::row_major> af[2];
        #pragma unroll
        for (int m = 0; m < 2; m++)
            wmma::load_matrix_sync(af[m], buf + (m * 16) * GLD + kk * 8, GLD);
        wmma::fragment<wmma::matrix_b, 16, 16, 8, wmma::precision::tf32, wmma::row_major> bf;
        #pragma unroll
        for (int j = 0; j < 2; j++) {
            wmma::load_matrix_sync(bf, W2 + (size_t)kk * 8 * HID + c0 + j * 16, HID);
            #pragma unroll
            for (int m = 0; m < 2; m++)
                wmma::mma_sync(acc[m][j], af[m], bf, acc[m][j]);
        }
    }
    __syncthreads();
    #pragma unroll
    for (int m = 0; m < 2; m++)
        #pragma unroll
        for (int j = 0; j < 2; j++)
            wmma::store_matrix_sync(buf + (m * 16) * GLD + c0 + j * 16,
                                    acc[m][j], GLD, wmma::mem_row_major);
    __syncthreads();

    {
        float bb = b2 ? b2[tid] : 0.0f;
        #pragma unroll 4
        for (int r = 0; r < NROWS; r++) {
            if (n0 + r < nnodes)
                out[(size_t)(n0 + r) * HID + tid] = buf[r * GLD + tid] + bb;
        }
    }
}

// ---------------------------------------------------------------------------
// Build LUT (fp32 SIMT, validated)
// ---------------------------------------------------------------------------
__global__ __launch_bounds__(NTHREADS) void build_table(
    const float* __restrict__ w1, const float* __restrict__ b1,
    const float* __restrict__ w2, const float* __restrict__ b2,
    float* __restrict__ table)
{
    __shared__ __align__(16) float eaT[NG * SPAD];
    __shared__ __align__(16) float t1T[HID * SPAD];
    __shared__ float C_s[TILE];

    const int tid = threadIdx.x;
    const int t0  = blockIdx.x * TILE;
    const float dx = DMAX / (float)(NT - 1);

    if (tid < TILE) {
        float d = (float)(t0 + tid) * dx;
        C_s[tid] = 0.5f * (cosf(d * (PI_F / CUTOFF_F)) + 1.0f);
    }

    const float step  = CUTOFF_F / (float)(NG - 1);
    const float coeff = -0.5f / (step * step);
    for (int idx = tid; idx < TILE * NG; idx += NTHREADS) {
        int e = idx / NG, g = idx % NG;
        float d = (float)(t0 + e) * dx;
        float diff = d - (float)g * step;
        eaT[g * SPAD + e] = expf(coeff * diff * diff);
    }
    __syncthreads();

    const int f = tid;
    float acc[TILE];
    {
        float bv = b1[f];
        #pragma unroll
        for (int e = 0; e < TILE; e++) acc[e] = bv;
        #pragma unroll 2
        for (int g = 0; g < NG; g++) {
            float wv = w1[g * HID + f];
            const float4* p = (const float4*)&eaT[g * SPAD];
            #pragma unroll
            for (int q = 0; q < TILE / 4; q++) {
                float4 v = p[q];
                acc[4*q+0] = fmaf(v.x, wv, acc[4*q+0]);
                acc[4*q+1] = fmaf(v.y, wv, acc[4*q+1]);
                acc[4*q+2] = fmaf(v.z, wv, acc[4*q+2]);
                acc[4*q+3] = fmaf(v.w, wv, acc[4*q+3]);
            }
        }
        #pragma unroll
        for (int e = 0; e < TILE; e++) t1T[f * SPAD + e] = ssp(acc[e]);
    }
    __syncthreads();
    {
        float bv = b2[f];
        #pragma unroll
        for (int e = 0; e < TILE; e++) acc[e] = bv;
        #pragma unroll 4
        for (int j = 0; j < HID; j++) {
            float wv = w2[j * HID + f];
            const float4* p = (const float4*)&t1T[j * SPAD];
            #pragma unroll
            for (int q = 0; q < TILE / 4; q++) {
                float4 v = p[q];
                acc[4*q+0] = fmaf(v.x, wv, acc[4*q+0]);
                acc[4*q+1] = fmaf(v.y, wv, acc[4*q+1]);
                acc[4*q+2] = fmaf(v.z, wv, acc[4*q+2]);
                acc[4*q+3] = fmaf(v.w, wv, acc[4*q+3]);
            }
        }
        #pragma unroll
        for (int e = 0; e < TILE; e++)
            table[(size_t)(t0 + e) * HID + f] = acc[e] * C_s[e];
    }
}

// ---------------------------------------------------------------------------
// Edge kernel (round-9 validated, byte-identical): float4 + 2-deep pipeline
// ---------------------------------------------------------------------------
#define EB 32
#define EDGE_SMEM_BYTES (EB * HID * 4)   // 32 KB

__global__ __launch_bounds__(NTHREADS, 4) void edge_lut_kernel(
    const float* __restrict__ x, const float* __restrict__ pos,
    const int* __restrict__ edge_index,
    const float* __restrict__ table,
    float* __restrict__ agg, int nedges)
{
    extern __shared__ float msg[];       // [EB][HID]
    __shared__ int   row_s[EB];
    __shared__ int   col_s[EB];
    __shared__ int   idx_s[EB];
    __shared__ float u_s[EB];

    const int tid   = threadIdx.x;
    const int grp   = tid >> 6;
    const int lane4 = tid & 63;
    const int e0    = blockIdx.x * EB;
    const float inv_dx = (float)(NT - 1) / DMAX;

    if (tid < EB) {
        int e = e0 + tid;
        int r = 0, c = 0, ti = 0;
        float u = 0.0f;
        if (e < nedges) {
            r = edge_index[e];
            c = edge_index[nedges + e];
            float dxp = pos[3*r+0] - pos[3*c+0];
            float dyp = pos[3*r+1] - pos[3*c+1];
            float dzp = pos[3*r+2] - pos[3*c+2];
            float d = sqrtf(dxp*dxp + dyp*dyp + dzp*dzp);
            float s = d * inv_dx;
            ti = (int)s;
            if (ti > NT - 2) ti = NT - 2;
            u = s - (float)ti;
        }
        row_s[tid] = r; col_s[tid] = c; idx_s[tid] = ti; u_s[tid] = u;
    }
    __syncthreads();

    const float4* tab4 = (const float4*)table;
    const float4* x4   = (const float4*)x;

    float4 a0, b0, v0;
    {
        int i = grp;
        size_t tbase = (size_t)idx_s[i] * (HID / 4) + lane4;
        a0 = tab4[tbase];
        b0 = tab4[tbase + HID / 4];
        v0 = x4[(size_t)row_s[i] * (HID / 4) + lane4];
    }
    #pragma unroll
    for (int it = 0; it < EB / 4; it++) {
        float4 a1, b1, v1;
        if (it < EB / 4 - 1) {
            int i = grp + (it + 1) * 4;
            size_t tbase = (size_t)idx_s[i] * (HID / 4) + lane4;
            a1 = tab4[tbase];
            b1 = tab4[tbase + HID / 4];
            v1 = x4[(size_t)row_s[i] * (HID / 4) + lane4];
        }
        int i = grp + it * 4;
        float u = u_s[i];
        float4 m;
        m.x = v0.x * fmaf(b0.x - a0.x, u, a0.x);
        m.y = v0.y * fmaf(b0.y - a0.y, u, a0.y);
        m.z = v0.z * fmaf(b0.z - a0.z, u, a0.z);
        m.w = v0.w * fmaf(b0.w - a0.w, u, a0.w);
        ((float4*)(msg + i * HID))[lane4] = m;
        a0 = a1; b0 = b1; v0 = v1;
    }
    __syncthreads();
    asm volatile("fence.proxy.async.shared::cta;" ::: "memory");

    if (tid < EB && (e0 + tid) < nedges) {
        unsigned saddr = (unsigned)__cvta_generic_to_shared(msg + tid * HID);
        float* gdst = agg + (size_t)col_s[tid] * HID;
        asm volatile(
            "cp.reduce.async.bulk.global.shared::cta.bulk_group.add.f32 [%0], [%1], %2;"
            :: "l"(gdst), "r"(saddr), "r"(HID * 4) : "memory");
        asm volatile("cp.async.bulk.commit_group;" ::: "memory");
        asm volatile("cp.async.bulk.wait_group 0;" ::: "memory");
    }
}

// ---------------------------------------------------------------------------
extern "C" void kernel_launch(void* const* d_in, const int* in_sizes, int n_in,
                              void* d_out, int out_size)
{
    const float* h      = (const float*)d_in[0];
    const float* pos    = (const float*)d_in[1];
    const float* lin1_w = (const float*)d_in[2];
    const float* lin2_w = (const float*)d_in[3];
    const float* lin2_b = (const float*)d_in[4];
    const float* mlp_w1 = (const float*)d_in[5];
    const float* mlp_b1 = (const float*)d_in[6];
    const float* mlp_w2 = (const float*)d_in[7];
    const float* mlp_b2 = (const float*)d_in[8];
    const float* lin_w  = (const float*)d_in[9];
    const float* lin_b  = (const float*)d_in[10];
    const int*   eidx   = (const int*)d_in[11];

    const int nnodes = in_sizes[0] / HID;
    const int nedges = in_sizes[11] / 2;

    float *xbuf = nullptr, *aggb = nullptr, *tabl = nullptr, *wtf = nullptr;
    cudaGetSymbolAddress((void**)&xbuf, g_x);
    cudaGetSymbolAddress((void**)&aggb, g_agg);
    cudaGetSymbolAddress((void**)&tabl, g_table);
    cudaGetSymbolAddress((void**)&wtf, g_wtf);

    float* out_f = (float*)d_out;

    static cudaStream_t s2 = nullptr;
    static cudaEvent_t evFork = nullptr, evJoin = nullptr;
    if (!s2) {
        cudaFuncSetAttribute(edge_lut_kernel,
                             cudaFuncAttributeMaxDynamicSharedMemorySize,
                             EDGE_SMEM_BYTES);
        cudaFuncSetAttribute(node_wmma,
                             cudaFuncAttributeMaxDynamicSharedMemorySize,
                             NODE_SMEM);
        cudaStreamCreateWithFlags(&s2, cudaStreamNonBlocking);
        cudaEventCreateWithFlags(&evFork, cudaEventDisableTiming);
        cudaEventCreateWithFlags(&evJoin, cudaEventDisableTiming);
    }

    const int nblk_wmma  = (nnodes + NROWS - 1) / NROWS;
    const int nblk_edges = (nedges + EB - 1) / EB;

    // fork: build_table + agg memset on s2, concurrent with prep+gemm1 on main
    cudaEventRecord(evFork, 0);
    cudaStreamWaitEvent(s2, evFork, 0);
    cudaMemsetAsync(aggb, 0, (size_t)nnodes * HID * sizeof(float), s2);
    build_table<<<NT / TILE, NTHREADS, 0, s2>>>(mlp_w1, mlp_b1, mlp_w2, mlp_b2, tabl);
    cudaEventRecord(evJoin, s2);

    prep_weights<<<dim3(HID, 3), HID>>>(lin1_w, lin2_w, lin_w);
    node_wmma<<<nblk_wmma, NTHREADS, NODE_SMEM>>>(
        h, wtf + 0 * HID * HID, nullptr, 0, nullptr, nullptr, xbuf, nnodes);

    cudaStreamWaitEvent(0, evJoin, 0);   // join before edge kernel

    edge_lut_kernel<<<nblk_edges, NTHREADS, EDGE_SMEM_BYTES>>>(
        xbuf, pos, eidx, tabl, aggb, nedges);

    node_wmma<<<nblk_wmma, NTHREADS, NODE_SMEM>>>(
        aggb, wtf + 1 * HID * HID, lin2_b, 1,
        wtf + 2 * HID * HID, lin_b, out_f, nnodes);

    if (out_size >= nnodes * HID + nnodes * 3) {
        cudaMemcpyAsync(out_f + (size_t)nnodes * HID, pos,
                        (size_t)nnodes * 3 * sizeof(float),
                        cudaMemcpyDeviceToDevice);
    }
}